// round 1
// baseline (speedup 1.0000x reference)
#include <cuda_runtime.h>

#define Bn 2
#define Tn 2048
#define Cn 1024
#define Hn 16
#define HDn 64
#define BTn (Bn*Tn)

// Scratch (no allocations allowed): head-major Q,K,V and attention output Y.
__device__ float g_q[Bn*Hn*Tn*HDn];
__device__ float g_k[Bn*Hn*Tn*HDn];
__device__ float g_v[Bn*Hn*Tn*HDn];
__device__ float g_y[(size_t)BTn*Cn];

// ---------------------------------------------------------------------------
// Tiled fp32 GEMM: out = A[M,K] @ W[K,N] + bias[N]
// OP=0: A = x, epilogue routes columns into g_q/g_k/g_v head-major layout.
// OP=1: A = g_y (ignores A param), epilogue writes row-major out.
// BM=BN=64, BK=16, 256 threads, 4x4 micro-tile per thread.
// ---------------------------------------------------------------------------
template<int OP>
__global__ __launch_bounds__(256)
void gemm_kernel(const float* __restrict__ A,
                 const float* __restrict__ W,
                 const float* __restrict__ bias,
                 float* __restrict__ out,
                 int M, int N, int K)
{
    constexpr int BM = 64, BN = 64, BK = 16;
    __shared__ __align__(16) float As[BK][BM];
    __shared__ __align__(16) float Bs[BK][BN];

    const float* Ap = (OP == 0) ? A : g_y;

    int tid = threadIdx.x;
    int bm = blockIdx.y * BM;
    int bn = blockIdx.x * BN;
    int ty = tid >> 4;          // 0..15 -> row group
    int tx = tid & 15;          // 0..15 -> col group

    // A tile load: float4 at row ar, cols [ac, ac+4)
    int ar = tid >> 2;          // 0..63
    int ac = (tid & 3) * 4;     // 0,4,8,12
    // W tile load: float4 at row br, cols [bc, bc+4)
    int br = tid >> 4;          // 0..15
    int bc = (tid & 15) * 4;    // 0..60

    float acc[4][4] = {};

    for (int k0 = 0; k0 < K; k0 += BK) {
        float4 a4 = *(const float4*)(Ap + (size_t)(bm + ar) * K + k0 + ac);
        As[ac + 0][ar] = a4.x;
        As[ac + 1][ar] = a4.y;
        As[ac + 2][ar] = a4.z;
        As[ac + 3][ar] = a4.w;
        float4 b4 = *(const float4*)(W + (size_t)(k0 + br) * N + bn + bc);
        *(float4*)&Bs[br][bc] = b4;
        __syncthreads();

        #pragma unroll
        for (int k = 0; k < BK; k++) {
            float4 av = *(const float4*)&As[k][ty * 4];
            float4 bv = *(const float4*)&Bs[k][tx * 4];
            float a[4] = {av.x, av.y, av.z, av.w};
            float b[4] = {bv.x, bv.y, bv.z, bv.w};
            #pragma unroll
            for (int i = 0; i < 4; i++)
                #pragma unroll
                for (int j = 0; j < 4; j++)
                    acc[i][j] += a[i] * b[j];
        }
        __syncthreads();
    }

    #pragma unroll
    for (int i = 0; i < 4; i++) {
        int m = bm + ty * 4 + i;
        #pragma unroll
        for (int j = 0; j < 4; j++) {
            int n = bn + tx * 4 + j;
            float v = acc[i][j] + bias[n];
            if (OP == 0) {
                int which = n / Cn;          // 0=q 1=k 2=v
                int cc = n - which * Cn;
                int h = cc / HDn;
                int d = cc - h * HDn;
                int b = m / Tn;
                int t = m - b * Tn;
                float* dst = (which == 0) ? g_q : (which == 1) ? g_k : g_v;
                dst[(((size_t)(b * Hn + h)) * Tn + t) * HDn + d] = v;
            } else {
                out[(size_t)m * N + n] = v;
            }
        }
    }
}

// ---------------------------------------------------------------------------
// Causal flash attention, fp32. One thread per query row (q + acc in regs).
// Block: 128 threads = 128 query rows. K/V tiles (64 keys) staged in SMEM.
// Lazy-max online softmax: rescale only when the running max improves.
// ---------------------------------------------------------------------------
__global__ __launch_bounds__(128)
void attn_kernel()
{
    __shared__ __align__(16) float Ks[64][HDn];
    __shared__ __align__(16) float Vs[64][HDn];

    int bh = blockIdx.y;                 // b*H + h
    int qbase = blockIdx.x * 128;
    int tid = threadIdx.x;
    int qi = qbase + tid;                // query index within T

    const float* qrow = g_q + ((size_t)bh * Tn + qi) * HDn;
    float q[HDn];
    #pragma unroll
    for (int i = 0; i < HDn / 4; i++) {
        float4 t4 = *(const float4*)(qrow + i * 4);
        q[i * 4 + 0] = t4.x; q[i * 4 + 1] = t4.y;
        q[i * 4 + 2] = t4.z; q[i * 4 + 3] = t4.w;
    }

    float acc[HDn] = {};
    float mrow = -1e30f, l = 0.f;
    const float scale = 0.125f;          // 1/sqrt(64)

    const float* kbase = g_k + (size_t)bh * Tn * HDn;
    const float* vbase = g_v + (size_t)bh * Tn * HDn;

    int ntiles = qbase / 64 + 2;         // covers keys up to qbase+127
    for (int kt = 0; kt < ntiles; kt++) {
        int ks = kt * 64;
        // Cooperative tile load: 64x64 floats each for K and V.
        #pragma unroll
        for (int i = 0; i < 8; i++) {
            int idx = tid + 128 * i;     // float4 index 0..1023
            int r = idx >> 4;
            int c4 = (idx & 15) * 4;
            *(float4*)&Ks[r][c4] = *(const float4*)(kbase + (size_t)(ks + r) * HDn + c4);
            *(float4*)&Vs[r][c4] = *(const float4*)(vbase + (size_t)(ks + r) * HDn + c4);
        }
        __syncthreads();

        int jmax = qi - ks + 1;
        if (jmax > 64) jmax = 64;
        for (int j = 0; j < jmax; j++) {
            // 4-way split dot product to break the FFMA dependency chain.
            const float4* kr = (const float4*)Ks[j];
            float s0 = 0.f, s1 = 0.f, s2 = 0.f, s3 = 0.f;
            #pragma unroll
            for (int i = 0; i < HDn / 16; i++) {
                float4 k0 = kr[i * 4 + 0];
                float4 k1 = kr[i * 4 + 1];
                float4 k2 = kr[i * 4 + 2];
                float4 k3 = kr[i * 4 + 3];
                s0 += q[i*16+ 0]*k0.x + q[i*16+ 1]*k0.y + q[i*16+ 2]*k0.z + q[i*16+ 3]*k0.w;
                s1 += q[i*16+ 4]*k1.x + q[i*16+ 5]*k1.y + q[i*16+ 6]*k1.z + q[i*16+ 7]*k1.w;
                s2 += q[i*16+ 8]*k2.x + q[i*16+ 9]*k2.y + q[i*16+10]*k2.z + q[i*16+11]*k2.w;
                s3 += q[i*16+12]*k3.x + q[i*16+13]*k3.y + q[i*16+14]*k3.z + q[i*16+15]*k3.w;
            }
            float s = ((s0 + s1) + (s2 + s3)) * scale;

            if (s > mrow) {
                float corr = __expf(mrow - s);   // 0 on first key (mrow=-1e30)
                l *= corr;
                #pragma unroll
                for (int d = 0; d < HDn; d++) acc[d] *= corr;
                mrow = s;
            }
            float p = __expf(s - mrow);
            l += p;
            const float4* vr = (const float4*)Vs[j];
            #pragma unroll
            for (int i = 0; i < HDn / 4; i++) {
                float4 v4 = vr[i];
                acc[i*4+0] += p * v4.x;
                acc[i*4+1] += p * v4.y;
                acc[i*4+2] += p * v4.z;
                acc[i*4+3] += p * v4.w;
            }
        }
        __syncthreads();
    }

    float inv = 1.f / l;
    int b = bh / Hn, h = bh % Hn;
    float* orow = g_y + ((size_t)b * Tn + qi) * Cn + h * HDn;
    #pragma unroll
    for (int i = 0; i < HDn / 4; i++) {
        float4 o4 = {acc[i*4+0]*inv, acc[i*4+1]*inv, acc[i*4+2]*inv, acc[i*4+3]*inv};
        *(float4*)(orow + i * 4) = o4;
    }
}

// ---------------------------------------------------------------------------
extern "C" void kernel_launch(void* const* d_in, const int* in_sizes, int n_in,
                              void* d_out, int out_size)
{
    const float* x      = (const float*)d_in[0];   // [B,T,C]
    const float* w_attn = (const float*)d_in[1];   // [C,3C]
    const float* b_attn = (const float*)d_in[2];   // [3C]
    const float* w_proj = (const float*)d_in[3];   // [C,C]
    const float* b_proj = (const float*)d_in[4];   // [C]
    float* out = (float*)d_out;                    // [B,T,C]

    // 1) QKV GEMM: [4096,1024] @ [1024,3072], route into g_q/g_k/g_v.
    {
        dim3 grid(3 * Cn / 64, BTn / 64);   // (48, 64)
        gemm_kernel<0><<<grid, 256>>>(x, w_attn, b_attn, nullptr,
                                      BTn, 3 * Cn, Cn);
    }
    // 2) Causal flash attention -> g_y [B,T,C].
    {
        dim3 grid(Tn / 128, Bn * Hn);       // (16, 32)
        attn_kernel<<<grid, 128>>>();
    }
    // 3) Projection GEMM: g_y [4096,1024] @ [1024,1024] + b_proj -> out.
    {
        dim3 grid(Cn / 64, BTn / 64);       // (16, 64)
        gemm_kernel<1><<<grid, 256>>>(nullptr, w_proj, b_proj, out,
                                      BTn, Cn, Cn);
    }
}

// round 2
// speedup vs baseline: 1.2450x; 1.2450x over previous
#include <cuda_runtime.h>
#include <mma.h>

using namespace nvcuda;

#define Bn 2
#define Tn 2048
#define Cn 1024
#define Hn 16
#define HDn 64
#define BTn (Bn*Tn)

// Scratch (no allocations allowed): head-major Q,K,V and attention output Y.
__device__ float g_q[Bn*Hn*Tn*HDn];
__device__ float g_k[Bn*Hn*Tn*HDn];
__device__ float g_v[Bn*Hn*Tn*HDn];
__device__ float g_y[(size_t)BTn*Cn];

// ---------------------------------------------------------------------------
// tf32 tensor-core GEMM: out = A[M,K] @ W[K,N] + bias[N]
// OP=0: A = x, epilogue routes columns into g_q/g_k/g_v head-major layout.
// OP=1: A = g_y (ignores A param), epilogue writes row-major out.
// BM=128, BN=64, BK=32. 256 threads = 8 warps, each warp owns a 32x32 tile
// as 2x2 wmma m16n16k8 tf32 fragments with fp32 accumulation.
// ---------------------------------------------------------------------------
template<int OP>
__global__ __launch_bounds__(256)
void gemm_tc(const float* __restrict__ A,
             const float* __restrict__ W,
             const float* __restrict__ bias,
             float* __restrict__ out,
             int M, int N, int K)
{
    constexpr int BM = 128, BN = 64, BK = 32;
    constexpr int LDA = BK + 4;   // 36 floats pitch (16B-aligned rows)
    constexpr int LDB = BN + 4;   // 68 floats pitch

    __shared__ __align__(16) float As[BM][LDA];    // row-major M x K tile
    __shared__ __align__(16) float Bs[BK][LDB];    // row-major K x N tile
    __shared__ __align__(16) float Epi[8][16][16]; // per-warp epilogue patch

    const float* Ap = (OP == 0) ? A : g_y;

    const int tid  = threadIdx.x;
    const int wid  = tid >> 5;
    const int lane = tid & 31;
    const int warp_m = wid & 3;   // 0..3 -> 32-row slab
    const int warp_n = wid >> 2;  // 0..1 -> 32-col slab
    const int bm = blockIdx.y * BM;
    const int bn = blockIdx.x * BN;

    wmma::fragment<wmma::accumulator, 16, 16, 8, float> acc[2][2];
    #pragma unroll
    for (int i = 0; i < 2; i++)
        #pragma unroll
        for (int j = 0; j < 2; j++)
            wmma::fill_fragment(acc[i][j], 0.0f);

    for (int k0 = 0; k0 < K; k0 += BK) {
        // Load A tile: 128x32 floats = 1024 float4, 4 per thread.
        #pragma unroll
        for (int i = 0; i < 4; i++) {
            int idx = tid + 256 * i;
            int r  = idx >> 3;
            int c4 = (idx & 7) * 4;
            float4 a4 = *(const float4*)(Ap + (size_t)(bm + r) * K + k0 + c4);
            *(float4*)&As[r][c4] = a4;
        }
        // Load W tile: 32x64 floats = 512 float4, 2 per thread.
        #pragma unroll
        for (int i = 0; i < 2; i++) {
            int idx = tid + 256 * i;
            int r  = idx >> 4;
            int c4 = (idx & 15) * 4;
            float4 b4 = *(const float4*)(W + (size_t)(k0 + r) * N + bn + c4);
            *(float4*)&Bs[r][c4] = b4;
        }
        __syncthreads();

        #pragma unroll
        for (int kk = 0; kk < BK; kk += 8) {
            wmma::fragment<wmma::matrix_a, 16, 16, 8, wmma::precision::tf32, wmma::row_major> af[2];
            wmma::fragment<wmma::matrix_b, 16, 16, 8, wmma::precision::tf32, wmma::row_major> bf[2];
            #pragma unroll
            for (int i = 0; i < 2; i++) {
                wmma::load_matrix_sync(af[i], &As[warp_m * 32 + i * 16][kk], LDA);
                #pragma unroll
                for (int e = 0; e < af[i].num_elements; e++)
                    af[i].x[e] = wmma::__float_to_tf32(af[i].x[e]);
            }
            #pragma unroll
            for (int j = 0; j < 2; j++) {
                wmma::load_matrix_sync(bf[j], &Bs[kk][warp_n * 32 + j * 16], LDB);
                #pragma unroll
                for (int e = 0; e < bf[j].num_elements; e++)
                    bf[j].x[e] = wmma::__float_to_tf32(bf[j].x[e]);
            }
            #pragma unroll
            for (int i = 0; i < 2; i++)
                #pragma unroll
                for (int j = 0; j < 2; j++)
                    wmma::mma_sync(acc[i][j], af[i], bf[j], acc[i][j]);
        }
        __syncthreads();
    }

    // Epilogue: stage each 16x16 fragment through SMEM, add bias, route.
    #pragma unroll
    for (int i = 0; i < 2; i++) {
        #pragma unroll
        for (int j = 0; j < 2; j++) {
            wmma::store_matrix_sync(&Epi[wid][0][0], acc[i][j], 16, wmma::mem_row_major);
            __syncwarp();
            #pragma unroll
            for (int e = 0; e < 8; e++) {
                int idx = lane + 32 * e;        // 0..255
                int r = idx >> 4;
                int c = idx & 15;
                int m = bm + warp_m * 32 + i * 16 + r;
                int n = bn + warp_n * 32 + j * 16 + c;
                float v = Epi[wid][r][c] + bias[n];
                if (OP == 0) {
                    int which = n / Cn;          // 0=q 1=k 2=v
                    int cc = n - which * Cn;
                    int h = cc / HDn;
                    int d = cc - h * HDn;
                    int b = m / Tn;
                    int t = m - b * Tn;
                    float* dst = (which == 0) ? g_q : (which == 1) ? g_k : g_v;
                    dst[(((size_t)(b * Hn + h)) * Tn + t) * HDn + d] = v;
                } else {
                    out[(size_t)m * N + n] = v;
                }
            }
            __syncwarp();
        }
    }
}

// ---------------------------------------------------------------------------
// Causal flash attention, fp32. One thread per query row (q + acc in regs).
// Block: 128 threads = 128 query rows. K/V tiles (64 keys) staged in SMEM.
// Lazy-max online softmax: rescale only when the running max improves.
// ---------------------------------------------------------------------------
__global__ __launch_bounds__(128)
void attn_kernel()
{
    __shared__ __align__(16) float Ks[64][HDn];
    __shared__ __align__(16) float Vs[64][HDn];

    int bh = blockIdx.y;                 // b*H + h
    int qbase = blockIdx.x * 128;
    int tid = threadIdx.x;
    int qi = qbase + tid;                // query index within T

    const float* qrow = g_q + ((size_t)bh * Tn + qi) * HDn;
    float q[HDn];
    #pragma unroll
    for (int i = 0; i < HDn / 4; i++) {
        float4 t4 = *(const float4*)(qrow + i * 4);
        q[i * 4 + 0] = t4.x; q[i * 4 + 1] = t4.y;
        q[i * 4 + 2] = t4.z; q[i * 4 + 3] = t4.w;
    }

    float acc[HDn] = {};
    float mrow = -1e30f, l = 0.f;
    const float scale = 0.125f;          // 1/sqrt(64)

    const float* kbase = g_k + (size_t)bh * Tn * HDn;
    const float* vbase = g_v + (size_t)bh * Tn * HDn;

    int ntiles = qbase / 64 + 2;         // covers keys up to qbase+127
    for (int kt = 0; kt < ntiles; kt++) {
        int ks = kt * 64;
        // Cooperative tile load: 64x64 floats each for K and V.
        #pragma unroll
        for (int i = 0; i < 8; i++) {
            int idx = tid + 128 * i;     // float4 index 0..1023
            int r = idx >> 4;
            int c4 = (idx & 15) * 4;
            *(float4*)&Ks[r][c4] = *(const float4*)(kbase + (size_t)(ks + r) * HDn + c4);
            *(float4*)&Vs[r][c4] = *(const float4*)(vbase + (size_t)(ks + r) * HDn + c4);
        }
        __syncthreads();

        int jmax = qi - ks + 1;
        if (jmax > 64) jmax = 64;
        for (int j = 0; j < jmax; j++) {
            // 4-way split dot product to break the FFMA dependency chain.
            const float4* kr = (const float4*)Ks[j];
            float s0 = 0.f, s1 = 0.f, s2 = 0.f, s3 = 0.f;
            #pragma unroll
            for (int i = 0; i < HDn / 16; i++) {
                float4 k0 = kr[i * 4 + 0];
                float4 k1 = kr[i * 4 + 1];
                float4 k2 = kr[i * 4 + 2];
                float4 k3 = kr[i * 4 + 3];
                s0 += q[i*16+ 0]*k0.x + q[i*16+ 1]*k0.y + q[i*16+ 2]*k0.z + q[i*16+ 3]*k0.w;
                s1 += q[i*16+ 4]*k1.x + q[i*16+ 5]*k1.y + q[i*16+ 6]*k1.z + q[i*16+ 7]*k1.w;
                s2 += q[i*16+ 8]*k2.x + q[i*16+ 9]*k2.y + q[i*16+10]*k2.z + q[i*16+11]*k2.w;
                s3 += q[i*16+12]*k3.x + q[i*16+13]*k3.y + q[i*16+14]*k3.z + q[i*16+15]*k3.w;
            }
            float s = ((s0 + s1) + (s2 + s3)) * scale;

            if (s > mrow) {
                float corr = __expf(mrow - s);   // 0 on first key (mrow=-1e30)
                l *= corr;
                #pragma unroll
                for (int d = 0; d < HDn; d++) acc[d] *= corr;
                mrow = s;
            }
            float p = __expf(s - mrow);
            l += p;
            const float4* vr = (const float4*)Vs[j];
            #pragma unroll
            for (int i = 0; i < HDn / 4; i++) {
                float4 v4 = vr[i];
                acc[i*4+0] += p * v4.x;
                acc[i*4+1] += p * v4.y;
                acc[i*4+2] += p * v4.z;
                acc[i*4+3] += p * v4.w;
            }
        }
        __syncthreads();
    }

    float inv = 1.f / l;
    int b = bh / Hn, h = bh % Hn;
    float* orow = g_y + ((size_t)b * Tn + qi) * Cn + h * HDn;
    #pragma unroll
    for (int i = 0; i < HDn / 4; i++) {
        float4 o4 = {acc[i*4+0]*inv, acc[i*4+1]*inv, acc[i*4+2]*inv, acc[i*4+3]*inv};
        *(float4*)(orow + i * 4) = o4;
    }
}

// ---------------------------------------------------------------------------
extern "C" void kernel_launch(void* const* d_in, const int* in_sizes, int n_in,
                              void* d_out, int out_size)
{
    const float* x      = (const float*)d_in[0];   // [B,T,C]
    const float* w_attn = (const float*)d_in[1];   // [C,3C]
    const float* b_attn = (const float*)d_in[2];   // [3C]
    const float* w_proj = (const float*)d_in[3];   // [C,C]
    const float* b_proj = (const float*)d_in[4];   // [C]
    float* out = (float*)d_out;                    // [B,T,C]

    // 1) QKV GEMM: [4096,1024] @ [1024,3072], route into g_q/g_k/g_v.
    {
        dim3 grid(3 * Cn / 64, BTn / 128);   // (48, 32)
        gemm_tc<0><<<grid, 256>>>(x, w_attn, b_attn, nullptr,
                                  BTn, 3 * Cn, Cn);
    }
    // 2) Causal flash attention -> g_y [B,T,C].
    {
        dim3 grid(Tn / 128, Bn * Hn);        // (16, 32)
        attn_kernel<<<grid, 128>>>();
    }
    // 3) Projection GEMM: g_y [4096,1024] @ [1024,1024] + b_proj -> out.
    {
        dim3 grid(Cn / 64, BTn / 128);       // (16, 32)
        gemm_tc<1><<<grid, 256>>>(nullptr, w_proj, b_proj, out,
                                  BTn, Cn, Cn);
    }
}

// round 3
// speedup vs baseline: 2.5098x; 2.0159x over previous
#include <cuda_runtime.h>
#include <mma.h>
#include <cstdint>

using namespace nvcuda;

#define Bn 2
#define Tn 2048
#define Cn 1024
#define Hn 16
#define HDn 64
#define BTn (Bn*Tn)

// Scratch (no allocations allowed): head-major Q,K,V and attention output Y.
__device__ float g_q[Bn*Hn*Tn*HDn];
__device__ float g_k[Bn*Hn*Tn*HDn];
__device__ float g_v[Bn*Hn*Tn*HDn];
__device__ float g_y[(size_t)BTn*Cn];

__device__ __forceinline__ uint32_t f2tf(float x) {
    uint32_t r;
    asm("cvt.rna.tf32.f32 %0, %1;" : "=r"(r) : "f"(x));
    return r;
}

// D = A@B + D, m16n8k8 tf32, A row-major, B col-major.
__device__ __forceinline__ void mma_tf32(float* d, const uint32_t* a, uint32_t b0, uint32_t b1) {
    asm volatile("mma.sync.aligned.m16n8k8.row.col.f32.tf32.tf32.f32 "
        "{%0,%1,%2,%3}, {%4,%5,%6,%7}, {%8,%9}, {%0,%1,%2,%3};\n"
        : "+f"(d[0]), "+f"(d[1]), "+f"(d[2]), "+f"(d[3])
        : "r"(a[0]), "r"(a[1]), "r"(a[2]), "r"(a[3]), "r"(b0), "r"(b1));
}

// ---------------------------------------------------------------------------
// tf32 tensor-core GEMM (unchanged from round 2).
// ---------------------------------------------------------------------------
template<int OP>
__global__ __launch_bounds__(256)
void gemm_tc(const float* __restrict__ A,
             const float* __restrict__ W,
             const float* __restrict__ bias,
             float* __restrict__ out,
             int M, int N, int K)
{
    constexpr int BM = 128, BN = 64, BK = 32;
    constexpr int LDA = BK + 4;
    constexpr int LDB = BN + 4;

    __shared__ __align__(16) float As[BM][LDA];
    __shared__ __align__(16) float Bs[BK][LDB];
    __shared__ __align__(16) float Epi[8][16][16];

    const float* Ap = (OP == 0) ? A : g_y;

    const int tid  = threadIdx.x;
    const int wid  = tid >> 5;
    const int lane = tid & 31;
    const int warp_m = wid & 3;
    const int warp_n = wid >> 2;
    const int bm = blockIdx.y * BM;
    const int bn = blockIdx.x * BN;

    wmma::fragment<wmma::accumulator, 16, 16, 8, float> acc[2][2];
    #pragma unroll
    for (int i = 0; i < 2; i++)
        #pragma unroll
        for (int j = 0; j < 2; j++)
            wmma::fill_fragment(acc[i][j], 0.0f);

    for (int k0 = 0; k0 < K; k0 += BK) {
        #pragma unroll
        for (int i = 0; i < 4; i++) {
            int idx = tid + 256 * i;
            int r  = idx >> 3;
            int c4 = (idx & 7) * 4;
            float4 a4 = *(const float4*)(Ap + (size_t)(bm + r) * K + k0 + c4);
            *(float4*)&As[r][c4] = a4;
        }
        #pragma unroll
        for (int i = 0; i < 2; i++) {
            int idx = tid + 256 * i;
            int r  = idx >> 4;
            int c4 = (idx & 15) * 4;
            float4 b4 = *(const float4*)(W + (size_t)(k0 + r) * N + bn + c4);
            *(float4*)&Bs[r][c4] = b4;
        }
        __syncthreads();

        #pragma unroll
        for (int kk = 0; kk < BK; kk += 8) {
            wmma::fragment<wmma::matrix_a, 16, 16, 8, wmma::precision::tf32, wmma::row_major> af[2];
            wmma::fragment<wmma::matrix_b, 16, 16, 8, wmma::precision::tf32, wmma::row_major> bf[2];
            #pragma unroll
            for (int i = 0; i < 2; i++) {
                wmma::load_matrix_sync(af[i], &As[warp_m * 32 + i * 16][kk], LDA);
                #pragma unroll
                for (int e = 0; e < af[i].num_elements; e++)
                    af[i].x[e] = wmma::__float_to_tf32(af[i].x[e]);
            }
            #pragma unroll
            for (int j = 0; j < 2; j++) {
                wmma::load_matrix_sync(bf[j], &Bs[kk][warp_n * 32 + j * 16], LDB);
                #pragma unroll
                for (int e = 0; e < bf[j].num_elements; e++)
                    bf[j].x[e] = wmma::__float_to_tf32(bf[j].x[e]);
            }
            #pragma unroll
            for (int i = 0; i < 2; i++)
                #pragma unroll
                for (int j = 0; j < 2; j++)
                    wmma::mma_sync(acc[i][j], af[i], bf[j], acc[i][j]);
        }
        __syncthreads();
    }

    #pragma unroll
    for (int i = 0; i < 2; i++) {
        #pragma unroll
        for (int j = 0; j < 2; j++) {
            wmma::store_matrix_sync(&Epi[wid][0][0], acc[i][j], 16, wmma::mem_row_major);
            __syncwarp();
            #pragma unroll
            for (int e = 0; e < 8; e++) {
                int idx = lane + 32 * e;
                int r = idx >> 4;
                int c = idx & 15;
                int m = bm + warp_m * 32 + i * 16 + r;
                int n = bn + warp_n * 32 + j * 16 + c;
                float v = Epi[wid][r][c] + bias[n];
                if (OP == 0) {
                    int which = n / Cn;
                    int cc = n - which * Cn;
                    int h = cc / HDn;
                    int d = cc - h * HDn;
                    int b = m / Tn;
                    int t = m - b * Tn;
                    float* dst = (which == 0) ? g_q : (which == 1) ? g_k : g_v;
                    dst[(((size_t)(b * Hn + h)) * Tn + t) * HDn + d] = v;
                } else {
                    out[(size_t)m * N + n] = v;
                }
            }
            __syncwarp();
        }
    }
}

// ---------------------------------------------------------------------------
// Flash attention on tensor cores (m16n8k8 tf32 mma).
// Block = 128 threads (4 warps) = 64 query rows; warp w owns rows w*16..+15.
// Loop over 64-key tiles: S=Q@K^T via mma, online softmax in registers
// (documented C-fragment layout: rows g, g+8), P staged through dead K SMEM,
// O += P@V via mma.
// ---------------------------------------------------------------------------
#define LDK 68   // K pitch: B-frag load pattern (4g+t) conflict-free
#define LDV 72   // V pitch: B-frag load pattern (8t+g) conflict-free

__global__ __launch_bounds__(128, 4)
void attn_mma()
{
    __shared__ __align__(16) float Ks[64 * LDK];
    __shared__ __align__(16) float Vs[64 * LDV];

    const int tid  = threadIdx.x;
    const int wid  = tid >> 5;
    const int lane = tid & 31;
    const int g = lane >> 2;      // group id (row within fragment)
    const int t = lane & 3;       // thread in group

    const int bh = blockIdx.x;                         // b*H + h
    const int Qi = (int)gridDim.y - 1 - (int)blockIdx.y; // heavy tiles first
    const int qbase = Qi * 64;

    const float* kg0 = g_k + (size_t)bh * Tn * HDn;
    const float* vg0 = g_v + (size_t)bh * Tn * HDn;

    // Q fragments (scaled by 1/sqrt(HD)=0.125, tf32), held for whole kernel.
    uint32_t qf[8][4];
    {
        const int r0 = qbase + wid * 16 + g;
        const float* p0 = g_q + ((size_t)bh * Tn + r0) * HDn;
        const float* p1 = p0 + 8 * HDn;
        #pragma unroll
        for (int c = 0; c < 8; c++) {
            qf[c][0] = f2tf(p0[8*c + t]     * 0.125f);
            qf[c][1] = f2tf(p1[8*c + t]     * 0.125f);
            qf[c][2] = f2tf(p0[8*c + t + 4] * 0.125f);
            qf[c][3] = f2tf(p1[8*c + t + 4] * 0.125f);
        }
    }

    float o[8][4];
    #pragma unroll
    for (int d = 0; d < 8; d++) { o[d][0]=0.f; o[d][1]=0.f; o[d][2]=0.f; o[d][3]=0.f; }
    float m0 = -1e30f, m1 = -1e30f, l0 = 0.f, l1 = 0.f;

    const int row0 = qbase + wid * 16 + g;   // global q row of frag elems 0,1
    const int row1 = row0 + 8;               // global q row of frag elems 2,3

    const int nkt = Qi + 1;
    for (int kt = 0; kt < nkt; kt++) {
        __syncthreads();   // prev iter done reading Ks(P) and Vs
        // Stage K/V tile (tf32-converted at store).
        {
            const float* kg = kg0 + (size_t)kt * 64 * HDn;
            const float* vg = vg0 + (size_t)kt * 64 * HDn;
            #pragma unroll
            for (int i = 0; i < 8; i++) {
                int idx = tid + 128 * i;
                int r  = idx >> 4;
                int c4 = (idx & 15) * 4;
                float4 a = *(const float4*)(kg + r * HDn + c4);
                uint32_t* dk = (uint32_t*)&Ks[r * LDK + c4];
                dk[0]=f2tf(a.x); dk[1]=f2tf(a.y); dk[2]=f2tf(a.z); dk[3]=f2tf(a.w);
                float4 b = *(const float4*)(vg + r * HDn + c4);
                uint32_t* dv = (uint32_t*)&Vs[r * LDV + c4];
                dv[0]=f2tf(b.x); dv[1]=f2tf(b.y); dv[2]=f2tf(b.z); dv[3]=f2tf(b.w);
            }
        }
        __syncthreads();

        // S = Q @ K^T : 8 n-tiles of 8 keys. B(k=dim,n=key) col-major:
        // b0 = K[8n+g][8c+t], b1 = K[8n+g][8c+t+4].
        float s[8][4];
        #pragma unroll
        for (int n = 0; n < 8; n++) { s[n][0]=0.f; s[n][1]=0.f; s[n][2]=0.f; s[n][3]=0.f; }
        #pragma unroll
        for (int c = 0; c < 8; c++) {
            #pragma unroll
            for (int n = 0; n < 8; n++) {
                const uint32_t* kp = (const uint32_t*)&Ks[(8*n + g) * LDK + 8*c + t];
                mma_tf32(s[n], qf[c], kp[0], kp[4]);
            }
        }

        // Causal mask on diagonal tile.
        if (kt == Qi) {
            #pragma unroll
            for (int n = 0; n < 8; n++) {
                int col = kt * 64 + 8*n + 2*t;
                if (col     > row0) s[n][0] = -1e30f;
                if (col + 1 > row0) s[n][1] = -1e30f;
                if (col     > row1) s[n][2] = -1e30f;
                if (col + 1 > row1) s[n][3] = -1e30f;
            }
        }

        // Online softmax (rows g and g+8).
        float mx0 = m0, mx1 = m1;
        #pragma unroll
        for (int n = 0; n < 8; n++) {
            mx0 = fmaxf(mx0, fmaxf(s[n][0], s[n][1]));
            mx1 = fmaxf(mx1, fmaxf(s[n][2], s[n][3]));
        }
        mx0 = fmaxf(mx0, __shfl_xor_sync(0xffffffff, mx0, 1));
        mx0 = fmaxf(mx0, __shfl_xor_sync(0xffffffff, mx0, 2));
        mx1 = fmaxf(mx1, __shfl_xor_sync(0xffffffff, mx1, 1));
        mx1 = fmaxf(mx1, __shfl_xor_sync(0xffffffff, mx1, 2));
        float corr0 = __expf(m0 - mx0);
        float corr1 = __expf(m1 - mx1);
        m0 = mx0; m1 = mx1;

        float rs0 = 0.f, rs1 = 0.f;
        #pragma unroll
        for (int n = 0; n < 8; n++) {
            s[n][0] = __expf(s[n][0] - m0);
            s[n][1] = __expf(s[n][1] - m0);
            s[n][2] = __expf(s[n][2] - m1);
            s[n][3] = __expf(s[n][3] - m1);
            rs0 += s[n][0] + s[n][1];
            rs1 += s[n][2] + s[n][3];
        }
        rs0 += __shfl_xor_sync(0xffffffff, rs0, 1);
        rs0 += __shfl_xor_sync(0xffffffff, rs0, 2);
        rs1 += __shfl_xor_sync(0xffffffff, rs1, 1);
        rs1 += __shfl_xor_sync(0xffffffff, rs1, 2);
        l0 = l0 * corr0 + rs0;
        l1 = l1 * corr1 + rs1;
        #pragma unroll
        for (int d = 0; d < 8; d++) {
            o[d][0] *= corr0; o[d][1] *= corr0;
            o[d][2] *= corr1; o[d][3] *= corr1;
        }

        __syncthreads();   // all warps done reading Ks for S
        // Stage P (tf32) into dead Ks region; warp-private 16-row slab.
        float* Ps = &Ks[(wid * 16) * LDK];
        #pragma unroll
        for (int n = 0; n < 8; n++) {
            *(uint2*)&Ps[g * LDK + 8*n + 2*t]       = make_uint2(f2tf(s[n][0]), f2tf(s[n][1]));
            *(uint2*)&Ps[(g + 8) * LDK + 8*n + 2*t] = make_uint2(f2tf(s[n][2]), f2tf(s[n][3]));
        }
        __syncwarp();

        // O += P @ V : A = P (16x8 keys chunk), B = V(k=key, n=dim).
        #pragma unroll
        for (int c = 0; c < 8; c++) {
            uint32_t a[4];
            a[0] = *(const uint32_t*)&Ps[g * LDK + 8*c + t];
            a[1] = *(const uint32_t*)&Ps[(g + 8) * LDK + 8*c + t];
            a[2] = *(const uint32_t*)&Ps[g * LDK + 8*c + t + 4];
            a[3] = *(const uint32_t*)&Ps[(g + 8) * LDK + 8*c + t + 4];
            #pragma unroll
            for (int d = 0; d < 8; d++) {
                uint32_t b0 = *(const uint32_t*)&Vs[(8*c + t) * LDV + 8*d + g];
                uint32_t b1 = *(const uint32_t*)&Vs[(8*c + t + 4) * LDV + 8*d + g];
                mma_tf32(o[d], a, b0, b1);
            }
        }
    }

    // Epilogue: O /= l, write head-major slice of g_y.
    float inv0 = 1.f / l0, inv1 = 1.f / l1;
    int b = bh / Hn, h = bh % Hn;
    float* y0 = g_y + ((size_t)b * Tn + row0) * Cn + h * HDn;
    float* y1 = g_y + ((size_t)b * Tn + row1) * Cn + h * HDn;
    #pragma unroll
    for (int d = 0; d < 8; d++) {
        *(float2*)&y0[8*d + 2*t] = make_float2(o[d][0] * inv0, o[d][1] * inv0);
        *(float2*)&y1[8*d + 2*t] = make_float2(o[d][2] * inv1, o[d][3] * inv1);
    }
}

// ---------------------------------------------------------------------------
extern "C" void kernel_launch(void* const* d_in, const int* in_sizes, int n_in,
                              void* d_out, int out_size)
{
    const float* x      = (const float*)d_in[0];
    const float* w_attn = (const float*)d_in[1];
    const float* b_attn = (const float*)d_in[2];
    const float* w_proj = (const float*)d_in[3];
    const float* b_proj = (const float*)d_in[4];
    float* out = (float*)d_out;

    // 1) QKV GEMM.
    {
        dim3 grid(3 * Cn / 64, BTn / 128);
        gemm_tc<0><<<grid, 256>>>(x, w_attn, b_attn, nullptr, BTn, 3 * Cn, Cn);
    }
    // 2) Causal flash attention (tensor cores) -> g_y.
    {
        dim3 grid(Bn * Hn, Tn / 64);   // x=bh, y=qtile (reversed inside)
        attn_mma<<<grid, 128>>>();
    }
    // 3) Projection GEMM.
    {
        dim3 grid(Cn / 64, BTn / 128);
        gemm_tc<1><<<grid, 256>>>(nullptr, w_proj, b_proj, out, BTn, Cn, Cn);
    }
}

// round 4
// speedup vs baseline: 4.1544x; 1.6553x over previous
#include <cuda_runtime.h>
#include <cstdint>

#define Bn 2
#define Tn 2048
#define Cn 1024
#define Hn 16
#define HDn 64
#define BTn (Bn*Tn)

// Scratch (no allocations allowed): head-major Q,K,V and attention output Y.
__device__ float g_q[Bn*Hn*Tn*HDn];
__device__ float g_k[Bn*Hn*Tn*HDn];
__device__ float g_v[Bn*Hn*Tn*HDn];
__device__ float g_y[(size_t)BTn*Cn];

__device__ __forceinline__ uint32_t f2tf(float x) {
    uint32_t r;
    asm("cvt.rna.tf32.f32 %0, %1;" : "=r"(r) : "f"(x));
    return r;
}
__device__ __forceinline__ float f2tff(float x) {
    return __uint_as_float(f2tf(x));
}

// D = A@B + D, m16n8k8 tf32, A row-major, B col-major.
__device__ __forceinline__ void mma_tf32(float* d, const uint32_t* a, uint32_t b0, uint32_t b1) {
    asm volatile("mma.sync.aligned.m16n8k8.row.col.f32.tf32.tf32.f32 "
        "{%0,%1,%2,%3}, {%4,%5,%6,%7}, {%8,%9}, {%0,%1,%2,%3};\n"
        : "+f"(d[0]), "+f"(d[1]), "+f"(d[2]), "+f"(d[3])
        : "r"(a[0]), "r"(a[1]), "r"(a[2]), "r"(a[3]), "r"(b0), "r"(b1));
}

// ---------------------------------------------------------------------------
// tf32 raw-mma GEMM: out = A[M,K] @ W[K,N] + bias[N]
// BM=128, BN=128, BK=16, double-buffered SMEM, tf32 cvt at store.
// 256 threads = 8 warps (2 x 4); each warp owns a 64x32 tile
// (4 m-frags x 4 n-frags of m16n8k8). One __syncthreads per BK iter.
// OP=0: epilogue routes columns into g_q/g_k/g_v head-major layout.
// OP=1: A = g_y, epilogue writes row-major out.
// ---------------------------------------------------------------------------
template<int OP>
__global__ __launch_bounds__(256, 2)
void gemm_tc2(const float* __restrict__ A,
              const float* __restrict__ W,
              const float* __restrict__ bias,
              float* __restrict__ out,
              int M, int N, int K)
{
    constexpr int BM = 128, BN = 128, BK = 16;
    constexpr int LDA = BK + 4;    // 20: A-frag lds (20g+t) conflict-free
    constexpr int LDB = BN + 8;    // 136: B-frag lds (8t+g) conflict-free

    __shared__ __align__(16) float As[2][BM * LDA];
    __shared__ __align__(16) float Bs[2][BK * LDB];

    const float* Ap = (OP == 0) ? A : g_y;

    const int tid  = threadIdx.x;
    const int wid  = tid >> 5;
    const int lane = tid & 31;
    const int g = lane >> 2;
    const int t = lane & 3;
    const int wm = wid >> 2;       // 0..1  -> 64-row slab
    const int wn = wid & 3;        // 0..3  -> 32-col slab
    const int bm = blockIdx.y * BM;
    const int bn = blockIdx.x * BN;

    // Global load / SMEM store coordinates (2 float4 each for A and B).
    const int ar = tid >> 2, ac = (tid & 3) * 4;     // A: rows ar, ar+64
    const int br = tid >> 5, bc = (tid & 31) * 4;    // B: rows br, br+8
    const float* pa0 = Ap + (size_t)(bm + ar) * K + ac;
    const float* pa1 = pa0 + (size_t)64 * K;
    const float* pb0 = W + (size_t)br * N + bn + bc;
    const float* pb1 = pb0 + (size_t)8 * N;
    const int sa0 = ar * LDA + ac, sa1 = sa0 + 64 * LDA;
    const int sb0 = br * LDB + bc, sb1 = sb0 + 8 * LDB;

    float acc[4][4][4];
    #pragma unroll
    for (int mi = 0; mi < 4; mi++)
        #pragma unroll
        for (int ni = 0; ni < 4; ni++)
            #pragma unroll
            for (int e = 0; e < 4; e++) acc[mi][ni][e] = 0.f;

    const int NITER = K / BK;

    // Stage tile 0 (ldg -> tf32 cvt -> sts).
    {
        float4 a0 = *(const float4*)pa0;
        float4 a1 = *(const float4*)pa1;
        float4 b0 = *(const float4*)pb0;
        float4 b1 = *(const float4*)pb1;
        float* As0 = As[0]; float* Bs0 = Bs[0];
        *(float4*)&As0[sa0] = make_float4(f2tff(a0.x), f2tff(a0.y), f2tff(a0.z), f2tff(a0.w));
        *(float4*)&As0[sa1] = make_float4(f2tff(a1.x), f2tff(a1.y), f2tff(a1.z), f2tff(a1.w));
        *(float4*)&Bs0[sb0] = make_float4(f2tff(b0.x), f2tff(b0.y), f2tff(b0.z), f2tff(b0.w));
        *(float4*)&Bs0[sb1] = make_float4(f2tff(b1.x), f2tff(b1.y), f2tff(b1.z), f2tff(b1.w));
    }
    __syncthreads();

    #pragma unroll 2
    for (int it = 0; it < NITER; it++) {
        const int cur = it & 1;
        float4 na0, na1, nb0, nb1;
        if (it + 1 < NITER) {
            int ko = (it + 1) * BK;
            na0 = *(const float4*)(pa0 + ko);
            na1 = *(const float4*)(pa1 + ko);
            nb0 = *(const float4*)(pb0 + (size_t)ko * N);
            nb1 = *(const float4*)(pb1 + (size_t)ko * N);
        }

        const float* Asb = As[cur];
        const float* Bsb = Bs[cur];
        #pragma unroll
        for (int kk = 0; kk < BK; kk += 8) {
            uint32_t af[4][4], bf[4][2];
            #pragma unroll
            for (int mi = 0; mi < 4; mi++) {
                int row = wm * 64 + mi * 16 + g;
                af[mi][0] = __float_as_uint(Asb[row * LDA + kk + t]);
                af[mi][1] = __float_as_uint(Asb[(row + 8) * LDA + kk + t]);
                af[mi][2] = __float_as_uint(Asb[row * LDA + kk + t + 4]);
                af[mi][3] = __float_as_uint(Asb[(row + 8) * LDA + kk + t + 4]);
            }
            #pragma unroll
            for (int ni = 0; ni < 4; ni++) {
                int col = wn * 32 + ni * 8 + g;
                bf[ni][0] = __float_as_uint(Bsb[(kk + t) * LDB + col]);
                bf[ni][1] = __float_as_uint(Bsb[(kk + t + 4) * LDB + col]);
            }
            #pragma unroll
            for (int mi = 0; mi < 4; mi++)
                #pragma unroll
                for (int ni = 0; ni < 4; ni++)
                    mma_tf32(acc[mi][ni], af[mi], bf[ni][0], bf[ni][1]);
        }

        if (it + 1 < NITER) {
            float* Asn = As[cur ^ 1]; float* Bsn = Bs[cur ^ 1];
            *(float4*)&Asn[sa0] = make_float4(f2tff(na0.x), f2tff(na0.y), f2tff(na0.z), f2tff(na0.w));
            *(float4*)&Asn[sa1] = make_float4(f2tff(na1.x), f2tff(na1.y), f2tff(na1.z), f2tff(na1.w));
            *(float4*)&Bsn[sb0] = make_float4(f2tff(nb0.x), f2tff(nb0.y), f2tff(nb0.z), f2tff(nb0.w));
            *(float4*)&Bsn[sb1] = make_float4(f2tff(nb1.x), f2tff(nb1.y), f2tff(nb1.z), f2tff(nb1.w));
        }
        __syncthreads();
    }

    // Epilogue: direct stores from C-fragment layout (rows g, g+8; cols 2t,2t+1).
    #pragma unroll
    for (int mi = 0; mi < 4; mi++) {
        int m0 = bm + wm * 64 + mi * 16 + g;
        #pragma unroll
        for (int ni = 0; ni < 4; ni++) {
            int n = bn + wn * 32 + ni * 8 + 2 * t;
            float2 bia = *(const float2*)&bias[n];
            float2 v0 = make_float2(acc[mi][ni][0] + bia.x, acc[mi][ni][1] + bia.y);
            float2 v1 = make_float2(acc[mi][ni][2] + bia.x, acc[mi][ni][3] + bia.y);
            if (OP == 0) {
                int which = n / Cn;          // 0=q 1=k 2=v
                int cc = n - which * Cn;
                int h = cc / HDn;
                int d = cc - h * HDn;
                float* dst = (which == 0) ? g_q : (which == 1) ? g_k : g_v;
                int b0i = m0 / Tn, t0 = m0 - b0i * Tn;
                *(float2*)&dst[(((size_t)(b0i * Hn + h)) * Tn + t0) * HDn + d] = v0;
                int m1 = m0 + 8;
                int b1i = m1 / Tn, t1 = m1 - b1i * Tn;
                *(float2*)&dst[(((size_t)(b1i * Hn + h)) * Tn + t1) * HDn + d] = v1;
            } else {
                *(float2*)&out[(size_t)m0 * N + n] = v0;
                *(float2*)&out[(size_t)(m0 + 8) * N + n] = v1;
            }
        }
    }
}

// ---------------------------------------------------------------------------
// Flash attention on tensor cores (m16n8k8 tf32 mma). Unchanged from round 3.
// ---------------------------------------------------------------------------
#define LDK 68
#define LDV 72

__global__ __launch_bounds__(128, 4)
void attn_mma()
{
    __shared__ __align__(16) float Ks[64 * LDK];
    __shared__ __align__(16) float Vs[64 * LDV];

    const int tid  = threadIdx.x;
    const int wid  = tid >> 5;
    const int lane = tid & 31;
    const int g = lane >> 2;
    const int t = lane & 3;

    const int bh = blockIdx.x;
    const int Qi = (int)gridDim.y - 1 - (int)blockIdx.y;
    const int qbase = Qi * 64;

    const float* kg0 = g_k + (size_t)bh * Tn * HDn;
    const float* vg0 = g_v + (size_t)bh * Tn * HDn;

    uint32_t qf[8][4];
    {
        const int r0 = qbase + wid * 16 + g;
        const float* p0 = g_q + ((size_t)bh * Tn + r0) * HDn;
        const float* p1 = p0 + 8 * HDn;
        #pragma unroll
        for (int c = 0; c < 8; c++) {
            qf[c][0] = f2tf(p0[8*c + t]     * 0.125f);
            qf[c][1] = f2tf(p1[8*c + t]     * 0.125f);
            qf[c][2] = f2tf(p0[8*c + t + 4] * 0.125f);
            qf[c][3] = f2tf(p1[8*c + t + 4] * 0.125f);
        }
    }

    float o[8][4];
    #pragma unroll
    for (int d = 0; d < 8; d++) { o[d][0]=0.f; o[d][1]=0.f; o[d][2]=0.f; o[d][3]=0.f; }
    float m0 = -1e30f, m1 = -1e30f, l0 = 0.f, l1 = 0.f;

    const int row0 = qbase + wid * 16 + g;
    const int row1 = row0 + 8;

    const int nkt = Qi + 1;
    for (int kt = 0; kt < nkt; kt++) {
        __syncthreads();
        {
            const float* kg = kg0 + (size_t)kt * 64 * HDn;
            const float* vg = vg0 + (size_t)kt * 64 * HDn;
            #pragma unroll
            for (int i = 0; i < 8; i++) {
                int idx = tid + 128 * i;
                int r  = idx >> 4;
                int c4 = (idx & 15) * 4;
                float4 a = *(const float4*)(kg + r * HDn + c4);
                uint32_t* dk = (uint32_t*)&Ks[r * LDK + c4];
                dk[0]=f2tf(a.x); dk[1]=f2tf(a.y); dk[2]=f2tf(a.z); dk[3]=f2tf(a.w);
                float4 b = *(const float4*)(vg + r * HDn + c4);
                uint32_t* dv = (uint32_t*)&Vs[r * LDV + c4];
                dv[0]=f2tf(b.x); dv[1]=f2tf(b.y); dv[2]=f2tf(b.z); dv[3]=f2tf(b.w);
            }
        }
        __syncthreads();

        float s[8][4];
        #pragma unroll
        for (int n = 0; n < 8; n++) { s[n][0]=0.f; s[n][1]=0.f; s[n][2]=0.f; s[n][3]=0.f; }
        #pragma unroll
        for (int c = 0; c < 8; c++) {
            #pragma unroll
            for (int n = 0; n < 8; n++) {
                const uint32_t* kp = (const uint32_t*)&Ks[(8*n + g) * LDK + 8*c + t];
                mma_tf32(s[n], qf[c], kp[0], kp[4]);
            }
        }

        if (kt == Qi) {
            #pragma unroll
            for (int n = 0; n < 8; n++) {
                int col = kt * 64 + 8*n + 2*t;
                if (col     > row0) s[n][0] = -1e30f;
                if (col + 1 > row0) s[n][1] = -1e30f;
                if (col     > row1) s[n][2] = -1e30f;
                if (col + 1 > row1) s[n][3] = -1e30f;
            }
        }

        float mx0 = m0, mx1 = m1;
        #pragma unroll
        for (int n = 0; n < 8; n++) {
            mx0 = fmaxf(mx0, fmaxf(s[n][0], s[n][1]));
            mx1 = fmaxf(mx1, fmaxf(s[n][2], s[n][3]));
        }
        mx0 = fmaxf(mx0, __shfl_xor_sync(0xffffffff, mx0, 1));
        mx0 = fmaxf(mx0, __shfl_xor_sync(0xffffffff, mx0, 2));
        mx1 = fmaxf(mx1, __shfl_xor_sync(0xffffffff, mx1, 1));
        mx1 = fmaxf(mx1, __shfl_xor_sync(0xffffffff, mx1, 2));
        float corr0 = __expf(m0 - mx0);
        float corr1 = __expf(m1 - mx1);
        m0 = mx0; m1 = mx1;

        float rs0 = 0.f, rs1 = 0.f;
        #pragma unroll
        for (int n = 0; n < 8; n++) {
            s[n][0] = __expf(s[n][0] - m0);
            s[n][1] = __expf(s[n][1] - m0);
            s[n][2] = __expf(s[n][2] - m1);
            s[n][3] = __expf(s[n][3] - m1);
            rs0 += s[n][0] + s[n][1];
            rs1 += s[n][2] + s[n][3];
        }
        rs0 += __shfl_xor_sync(0xffffffff, rs0, 1);
        rs0 += __shfl_xor_sync(0xffffffff, rs0, 2);
        rs1 += __shfl_xor_sync(0xffffffff, rs1, 1);
        rs1 += __shfl_xor_sync(0xffffffff, rs1, 2);
        l0 = l0 * corr0 + rs0;
        l1 = l1 * corr1 + rs1;
        #pragma unroll
        for (int d = 0; d < 8; d++) {
            o[d][0] *= corr0; o[d][1] *= corr0;
            o[d][2] *= corr1; o[d][3] *= corr1;
        }

        __syncthreads();
        float* Ps = &Ks[(wid * 16) * LDK];
        #pragma unroll
        for (int n = 0; n < 8; n++) {
            *(uint2*)&Ps[g * LDK + 8*n + 2*t]       = make_uint2(f2tf(s[n][0]), f2tf(s[n][1]));
            *(uint2*)&Ps[(g + 8) * LDK + 8*n + 2*t] = make_uint2(f2tf(s[n][2]), f2tf(s[n][3]));
        }
        __syncwarp();

        #pragma unroll
        for (int c = 0; c < 8; c++) {
            uint32_t a[4];
            a[0] = *(const uint32_t*)&Ps[g * LDK + 8*c + t];
            a[1] = *(const uint32_t*)&Ps[(g + 8) * LDK + 8*c + t];
            a[2] = *(const uint32_t*)&Ps[g * LDK + 8*c + t + 4];
            a[3] = *(const uint32_t*)&Ps[(g + 8) * LDK + 8*c + t + 4];
            #pragma unroll
            for (int d = 0; d < 8; d++) {
                uint32_t b0 = *(const uint32_t*)&Vs[(8*c + t) * LDV + 8*d + g];
                uint32_t b1 = *(const uint32_t*)&Vs[(8*c + t + 4) * LDV + 8*d + g];
                mma_tf32(o[d], a, b0, b1);
            }
        }
    }

    float inv0 = 1.f / l0, inv1 = 1.f / l1;
    int b = bh / Hn, h = bh % Hn;
    float* y0 = g_y + ((size_t)b * Tn + row0) * Cn + h * HDn;
    float* y1 = g_y + ((size_t)b * Tn + row1) * Cn + h * HDn;
    #pragma unroll
    for (int d = 0; d < 8; d++) {
        *(float2*)&y0[8*d + 2*t] = make_float2(o[d][0] * inv0, o[d][1] * inv0);
        *(float2*)&y1[8*d + 2*t] = make_float2(o[d][2] * inv1, o[d][3] * inv1);
    }
}

// ---------------------------------------------------------------------------
extern "C" void kernel_launch(void* const* d_in, const int* in_sizes, int n_in,
                              void* d_out, int out_size)
{
    const float* x      = (const float*)d_in[0];
    const float* w_attn = (const float*)d_in[1];
    const float* b_attn = (const float*)d_in[2];
    const float* w_proj = (const float*)d_in[3];
    const float* b_proj = (const float*)d_in[4];
    float* out = (float*)d_out;

    // 1) QKV GEMM: [4096,1024]@[1024,3072] -> g_q/g_k/g_v (head-major).
    {
        dim3 grid(3 * Cn / 128, BTn / 128);   // (24, 32)
        gemm_tc2<0><<<grid, 256>>>(x, w_attn, b_attn, nullptr, BTn, 3 * Cn, Cn);
    }
    // 2) Causal flash attention (tensor cores) -> g_y.
    {
        dim3 grid(Bn * Hn, Tn / 64);
        attn_mma<<<grid, 128>>>();
    }
    // 3) Projection GEMM: g_y @ w_proj + b_proj -> out.
    {
        dim3 grid(Cn / 128, BTn / 128);       // (8, 32)
        gemm_tc2<1><<<grid, 256>>>(nullptr, w_proj, b_proj, out, BTn, Cn, Cn);
    }
}

// round 6
// speedup vs baseline: 4.3999x; 1.0591x over previous
#include <cuda_runtime.h>
#include <cstdint>

#define Bn 2
#define Tn 2048
#define Cn 1024
#define Hn 16
#define HDn 64
#define BTn (Bn*Tn)

// Scratch (no allocations allowed).
__device__ float g_q[Bn*Hn*Tn*HDn];
__device__ float g_k[Bn*Hn*Tn*HDn];
__device__ float g_v[Bn*Hn*Tn*HDn];
__device__ float g_y[(size_t)BTn*Cn];     // attention out (tf32-rounded)
__device__ float g_xr[(size_t)BTn*Cn];    // x, tf32-rounded
__device__ float g_wt[3*Cn*Cn];           // w_attn^T [3C, C], tf32-rounded
__device__ float g_wp[Cn*Cn];             // w_proj^T [C, C],  tf32-rounded

__device__ __forceinline__ uint32_t f2tf(float x) {
    uint32_t r;
    asm("cvt.rna.tf32.f32 %0, %1;" : "=r"(r) : "f"(x));
    return r;
}
__device__ __forceinline__ float f2tff(float x) { return __uint_as_float(f2tf(x)); }

__device__ __forceinline__ uint32_t smem_u32(const void* p) {
    uint32_t a;
    asm("{ .reg .u64 t; cvta.to.shared.u64 t, %1; cvt.u32.u64 %0, t; }"
        : "=r"(a) : "l"(p));
    return a;
}

__device__ __forceinline__ void cp16(uint32_t sdst, const void* gsrc) {
    asm volatile("cp.async.cg.shared.global [%0], [%1], 16;"
                 :: "r"(sdst), "l"(gsrc) : "memory");
}
#define CP_COMMIT() asm volatile("cp.async.commit_group;" ::: "memory")
#define CP_WAIT(n)  asm volatile("cp.async.wait_group %0;" :: "n"(n) : "memory")

// D = A@B + D, m16n8k8 tf32, A row-major, B col-major.
__device__ __forceinline__ void mma_tf32(float* d, const uint32_t* a, uint32_t b0, uint32_t b1) {
    asm volatile("mma.sync.aligned.m16n8k8.row.col.f32.tf32.tf32.f32 "
        "{%0,%1,%2,%3}, {%4,%5,%6,%7}, {%8,%9}, {%0,%1,%2,%3};\n"
        : "+f"(d[0]), "+f"(d[1]), "+f"(d[2]), "+f"(d[3])
        : "r"(a[0]), "r"(a[1]), "r"(a[2]), "r"(a[3]), "r"(b0), "r"(b1));
}

// ---------------------------------------------------------------------------
// Prep: tf32-round a float array (float4 vectorized).
// ---------------------------------------------------------------------------
__global__ void round_tf32(const float* __restrict__ src, float* __restrict__ dst, int n4)
{
    int i = blockIdx.x * blockDim.x + threadIdx.x;
    if (i < n4) {
        float4 v = ((const float4*)src)[i];
        ((float4*)dst)[i] = make_float4(f2tff(v.x), f2tff(v.y), f2tff(v.z), f2tff(v.w));
    }
}

// Prep: transpose + tf32-round. dst[n][k] = tf32(src[k][n]); src [K,N] row-major.
__global__ void transpose_w(const float* __restrict__ src, float* __restrict__ dst,
                            int K, int N)
{
    __shared__ float t[32][33];
    int bx = blockIdx.x * 32;   // n
    int by = blockIdx.y * 32;   // k
    int x = threadIdx.x, y = threadIdx.y;
    #pragma unroll
    for (int i = 0; i < 32; i += 8)
        t[y + i][x] = src[(size_t)(by + y + i) * N + bx + x];
    __syncthreads();
    #pragma unroll
    for (int i = 0; i < 32; i += 8)
        dst[(size_t)(bx + y + i) * K + by + x] = f2tff(t[x][y + i]);
}

// ---------------------------------------------------------------------------
// tf32 mma.sync GEMM, cp.async pipeline, pre-rounded inputs (no cvt in loop).
// out[M,N] = A[M,K] @ WT[N,K]^T + bias[N].
// Block 128x128, BK=32, 4 warps, each warp owns 64x64 (4 m-frags x 8 n-frags).
// A/B SMEM tiles are [128][36] (pitch 36 -> all fragment LDS conflict-free).
// OP=0: A = g_xr, epilogue routes into g_q/g_k/g_v head-major.
// OP=1: A = g_y,  epilogue writes row-major out.
// ---------------------------------------------------------------------------
#define LDT 36
#define TILE_B (128 * LDT * 4)             // 18432 bytes per tile buffer
#define GSMEM_SZ (4 * TILE_B)              // A0 A1 B0 B1

template<int OP>
__global__ __launch_bounds__(128, 2)
void gemm_cp(const float* __restrict__ A_,
             const float* __restrict__ WT,
             const float* __restrict__ bias,
             float* __restrict__ out,
             int M, int N, int K)
{
    extern __shared__ __align__(16) float smem[];
    float* Asb[2] = { smem,            smem + 128 * LDT };
    float* Bsb[2] = { smem + 256 * LDT, smem + 384 * LDT };

    const float* A = (OP == 0) ? g_xr : g_y;
    (void)A_;

    const int tid  = threadIdx.x;
    const int wid  = tid >> 5;
    const int lane = tid & 31;
    const int g = lane >> 2;
    const int t = lane & 3;
    const int wm = wid >> 1;       // 0..1 -> 64-row slab
    const int wn = wid & 1;        // 0..1 -> 64-col slab
    const int bm = blockIdx.y * 128;
    const int bn = blockIdx.x * 128;

    // cp.async coords: thread handles rows r0+16i (i=0..7), col chunk c4.
    const int r0 = tid >> 3;             // 0..15
    const int c4 = (tid & 7) * 4;        // 0,4,...,28
    const float* pa = A  + (size_t)(bm + r0) * K + c4;
    const float* pb = WT + (size_t)(bn + r0) * K + c4;
    const uint32_t sA[2] = { smem_u32(Asb[0]) + (uint32_t)(r0 * LDT + c4) * 4,
                             smem_u32(Asb[1]) + (uint32_t)(r0 * LDT + c4) * 4 };
    const uint32_t sB[2] = { smem_u32(Bsb[0]) + (uint32_t)(r0 * LDT + c4) * 4,
                             smem_u32(Bsb[1]) + (uint32_t)(r0 * LDT + c4) * 4 };

    float acc[4][8][4];
    #pragma unroll
    for (int mi = 0; mi < 4; mi++)
        #pragma unroll
        for (int ni = 0; ni < 8; ni++)
            #pragma unroll
            for (int e = 0; e < 4; e++) acc[mi][ni][e] = 0.f;

    const int NIT = K / 32;

    // Stage tile 0.
    #pragma unroll
    for (int i = 0; i < 8; i++) {
        cp16(sA[0] + i * 16 * LDT * 4, pa + (size_t)(16 * i) * K);
        cp16(sB[0] + i * 16 * LDT * 4, pb + (size_t)(16 * i) * K);
    }
    CP_COMMIT();

    for (int it = 0; it < NIT; it++) {
        const int cur = it & 1;
        if (it + 1 < NIT) {
            const int nxt = cur ^ 1;
            const size_t ko = (size_t)(it + 1) * 32;
            #pragma unroll
            for (int i = 0; i < 8; i++) {
                cp16(sA[nxt] + i * 16 * LDT * 4, pa + (size_t)(16 * i) * K + ko);
                cp16(sB[nxt] + i * 16 * LDT * 4, pb + (size_t)(16 * i) * K + ko);
            }
            CP_COMMIT();
            CP_WAIT(1);
        } else {
            CP_WAIT(0);
        }
        __syncthreads();

        const float* As = Asb[cur];
        const float* Bs = Bsb[cur];
        #pragma unroll
        for (int kk = 0; kk < 4; kk++) {
            uint32_t af[4][4], bf[8][2];
            #pragma unroll
            for (int mi = 0; mi < 4; mi++) {
                int row = wm * 64 + mi * 16 + g;
                af[mi][0] = __float_as_uint(As[row * LDT + kk * 8 + t]);
                af[mi][1] = __float_as_uint(As[(row + 8) * LDT + kk * 8 + t]);
                af[mi][2] = __float_as_uint(As[row * LDT + kk * 8 + t + 4]);
                af[mi][3] = __float_as_uint(As[(row + 8) * LDT + kk * 8 + t + 4]);
            }
            #pragma unroll
            for (int ni = 0; ni < 8; ni++) {
                int col = wn * 64 + ni * 8 + g;
                bf[ni][0] = __float_as_uint(Bs[col * LDT + kk * 8 + t]);
                bf[ni][1] = __float_as_uint(Bs[col * LDT + kk * 8 + t + 4]);
            }
            #pragma unroll
            for (int mi = 0; mi < 4; mi++)
                #pragma unroll
                for (int ni = 0; ni < 8; ni++)
                    mma_tf32(acc[mi][ni], af[mi], bf[ni][0], bf[ni][1]);
        }
        __syncthreads();
    }

    // Epilogue: direct stores from C-fragment layout (rows g,g+8; cols 2t,2t+1).
    #pragma unroll
    for (int mi = 0; mi < 4; mi++) {
        int m0 = bm + wm * 64 + mi * 16 + g;
        #pragma unroll
        for (int ni = 0; ni < 8; ni++) {
            int n = bn + wn * 64 + ni * 8 + 2 * t;
            float2 bia = *(const float2*)&bias[n];
            float2 v0 = make_float2(acc[mi][ni][0] + bia.x, acc[mi][ni][1] + bia.y);
            float2 v1 = make_float2(acc[mi][ni][2] + bia.x, acc[mi][ni][3] + bia.y);
            if (OP == 0) {
                int which = n >> 10;         // 0=q 1=k 2=v
                int cc = n & (Cn - 1);
                int h = cc >> 6;
                int d = cc & (HDn - 1);
                float* dst = (which == 0) ? g_q : (which == 1) ? g_k : g_v;
                int b0i = m0 >> 11, t0 = m0 & (Tn - 1);
                *(float2*)&dst[(((size_t)(b0i * Hn + h)) * Tn + t0) * HDn + d] = v0;
                int m1 = m0 + 8;
                int b1i = m1 >> 11, t1 = m1 & (Tn - 1);
                *(float2*)&dst[(((size_t)(b1i * Hn + h)) * Tn + t1) * HDn + d] = v1;
            } else {
                *(float2*)&out[(size_t)m0 * N + n] = v0;
                *(float2*)&out[(size_t)(m0 + 8) * N + n] = v1;
            }
        }
    }
}

// ---------------------------------------------------------------------------
// Flash attention on tensor cores (m16n8k8 tf32 mma). Same as round 4, but
// epilogue writes tf32-rounded y so the proj GEMM needs no conversion.
// ---------------------------------------------------------------------------
#define LDK 68
#define LDV 72

__global__ __launch_bounds__(128, 4)
void attn_mma()
{
    __shared__ __align__(16) float Ks[64 * LDK];
    __shared__ __align__(16) float Vs[64 * LDV];

    const int tid  = threadIdx.x;
    const int wid  = tid >> 5;
    const int lane = tid & 31;
    const int g = lane >> 2;
    const int t = lane & 3;

    const int bh = blockIdx.x;
    const int Qi = (int)gridDim.y - 1 - (int)blockIdx.y;
    const int qbase = Qi * 64;

    const float* kg0 = g_k + (size_t)bh * Tn * HDn;
    const float* vg0 = g_v + (size_t)bh * Tn * HDn;

    uint32_t qf[8][4];
    {
        const int r0 = qbase + wid * 16 + g;
        const float* p0 = g_q + ((size_t)bh * Tn + r0) * HDn;
        const float* p1 = p0 + 8 * HDn;
        #pragma unroll
        for (int c = 0; c < 8; c++) {
            qf[c][0] = f2tf(p0[8*c + t]     * 0.125f);
            qf[c][1] = f2tf(p1[8*c + t]     * 0.125f);
            qf[c][2] = f2tf(p0[8*c + t + 4] * 0.125f);
            qf[c][3] = f2tf(p1[8*c + t + 4] * 0.125f);
        }
    }

    float o[8][4];
    #pragma unroll
    for (int d = 0; d < 8; d++) { o[d][0]=0.f; o[d][1]=0.f; o[d][2]=0.f; o[d][3]=0.f; }
    float m0 = -1e30f, m1 = -1e30f, l0 = 0.f, l1 = 0.f;

    const int row0 = qbase + wid * 16 + g;
    const int row1 = row0 + 8;

    const int nkt = Qi + 1;
    for (int kt = 0; kt < nkt; kt++) {
        __syncthreads();
        {
            const float* kg = kg0 + (size_t)kt * 64 * HDn;
            const float* vg = vg0 + (size_t)kt * 64 * HDn;
            #pragma unroll
            for (int i = 0; i < 8; i++) {
                int idx = tid + 128 * i;
                int r  = idx >> 4;
                int c4 = (idx & 15) * 4;
                float4 a = *(const float4*)(kg + r * HDn + c4);
                uint32_t* dk = (uint32_t*)&Ks[r * LDK + c4];
                dk[0]=f2tf(a.x); dk[1]=f2tf(a.y); dk[2]=f2tf(a.z); dk[3]=f2tf(a.w);
                float4 b = *(const float4*)(vg + r * HDn + c4);
                uint32_t* dv = (uint32_t*)&Vs[r * LDV + c4];
                dv[0]=f2tf(b.x); dv[1]=f2tf(b.y); dv[2]=f2tf(b.z); dv[3]=f2tf(b.w);
            }
        }
        __syncthreads();

        float s[8][4];
        #pragma unroll
        for (int n = 0; n < 8; n++) { s[n][0]=0.f; s[n][1]=0.f; s[n][2]=0.f; s[n][3]=0.f; }
        #pragma unroll
        for (int c = 0; c < 8; c++) {
            #pragma unroll
            for (int n = 0; n < 8; n++) {
                const uint32_t* kp = (const uint32_t*)&Ks[(8*n + g) * LDK + 8*c + t];
                mma_tf32(s[n], qf[c], kp[0], kp[4]);
            }
        }

        if (kt == Qi) {
            #pragma unroll
            for (int n = 0; n < 8; n++) {
                int col = kt * 64 + 8*n + 2*t;
                if (col     > row0) s[n][0] = -1e30f;
                if (col + 1 > row0) s[n][1] = -1e30f;
                if (col     > row1) s[n][2] = -1e30f;
                if (col + 1 > row1) s[n][3] = -1e30f;
            }
        }

        float mx0 = m0, mx1 = m1;
        #pragma unroll
        for (int n = 0; n < 8; n++) {
            mx0 = fmaxf(mx0, fmaxf(s[n][0], s[n][1]));
            mx1 = fmaxf(mx1, fmaxf(s[n][2], s[n][3]));
        }
        mx0 = fmaxf(mx0, __shfl_xor_sync(0xffffffff, mx0, 1));
        mx0 = fmaxf(mx0, __shfl_xor_sync(0xffffffff, mx0, 2));
        mx1 = fmaxf(mx1, __shfl_xor_sync(0xffffffff, mx1, 1));
        mx1 = fmaxf(mx1, __shfl_xor_sync(0xffffffff, mx1, 2));
        float corr0 = __expf(m0 - mx0);
        float corr1 = __expf(m1 - mx1);
        m0 = mx0; m1 = mx1;

        float rs0 = 0.f, rs1 = 0.f;
        #pragma unroll
        for (int n = 0; n < 8; n++) {
            s[n][0] = __expf(s[n][0] - m0);
            s[n][1] = __expf(s[n][1] - m0);
            s[n][2] = __expf(s[n][2] - m1);
            s[n][3] = __expf(s[n][3] - m1);
            rs0 += s[n][0] + s[n][1];
            rs1 += s[n][2] + s[n][3];
        }
        rs0 += __shfl_xor_sync(0xffffffff, rs0, 1);
        rs0 += __shfl_xor_sync(0xffffffff, rs0, 2);
        rs1 += __shfl_xor_sync(0xffffffff, rs1, 1);
        rs1 += __shfl_xor_sync(0xffffffff, rs1, 2);
        l0 = l0 * corr0 + rs0;
        l1 = l1 * corr1 + rs1;
        #pragma unroll
        for (int d = 0; d < 8; d++) {
            o[d][0] *= corr0; o[d][1] *= corr0;
            o[d][2] *= corr1; o[d][3] *= corr1;
        }

        __syncthreads();
        float* Ps = &Ks[(wid * 16) * LDK];
        #pragma unroll
        for (int n = 0; n < 8; n++) {
            *(uint2*)&Ps[g * LDK + 8*n + 2*t]       = make_uint2(f2tf(s[n][0]), f2tf(s[n][1]));
            *(uint2*)&Ps[(g + 8) * LDK + 8*n + 2*t] = make_uint2(f2tf(s[n][2]), f2tf(s[n][3]));
        }
        __syncwarp();

        #pragma unroll
        for (int c = 0; c < 8; c++) {
            uint32_t a[4];
            a[0] = *(const uint32_t*)&Ps[g * LDK + 8*c + t];
            a[1] = *(const uint32_t*)&Ps[(g + 8) * LDK + 8*c + t];
            a[2] = *(const uint32_t*)&Ps[g * LDK + 8*c + t + 4];
            a[3] = *(const uint32_t*)&Ps[(g + 8) * LDK + 8*c + t + 4];
            #pragma unroll
            for (int d = 0; d < 8; d++) {
                uint32_t b0 = *(const uint32_t*)&Vs[(8*c + t) * LDV + 8*d + g];
                uint32_t b1 = *(const uint32_t*)&Vs[(8*c + t + 4) * LDV + 8*d + g];
                mma_tf32(o[d], a, b0, b1);
            }
        }
    }

    float inv0 = 1.f / l0, inv1 = 1.f / l1;
    int b = bh / Hn, h = bh % Hn;
    float* y0 = g_y + ((size_t)b * Tn + row0) * Cn + h * HDn;
    float* y1 = g_y + ((size_t)b * Tn + row1) * Cn + h * HDn;
    #pragma unroll
    for (int d = 0; d < 8; d++) {
        *(float2*)&y0[8*d + 2*t] = make_float2(f2tff(o[d][0] * inv0), f2tff(o[d][1] * inv0));
        *(float2*)&y1[8*d + 2*t] = make_float2(f2tff(o[d][2] * inv1), f2tff(o[d][3] * inv1));
    }
}

// ---------------------------------------------------------------------------
extern "C" void kernel_launch(void* const* d_in, const int* in_sizes, int n_in,
                              void* d_out, int out_size)
{
    const float* x      = (const float*)d_in[0];
    const float* w_attn = (const float*)d_in[1];
    const float* b_attn = (const float*)d_in[2];
    const float* w_proj = (const float*)d_in[3];
    const float* b_proj = (const float*)d_in[4];
    float* out = (float*)d_out;

    cudaFuncSetAttribute(gemm_cp<0>, cudaFuncAttributeMaxDynamicSharedMemorySize, GSMEM_SZ);
    cudaFuncSetAttribute(gemm_cp<1>, cudaFuncAttributeMaxDynamicSharedMemorySize, GSMEM_SZ);

    float* xr; cudaGetSymbolAddress((void**)&xr, g_xr);
    float* wt; cudaGetSymbolAddress((void**)&wt, g_wt);
    float* wp; cudaGetSymbolAddress((void**)&wp, g_wp);

    // 0) Prep: tf32-round x; transpose+round weights.
    {
        int n4 = BTn * Cn / 4;
        round_tf32<<<(n4 + 255) / 256, 256>>>(x, xr, n4);
        dim3 blk(32, 8);
        transpose_w<<<dim3(3 * Cn / 32, Cn / 32), blk>>>(w_attn, wt, Cn, 3 * Cn);
        transpose_w<<<dim3(Cn / 32, Cn / 32), blk>>>(w_proj, wp, Cn, Cn);
    }
    // 1) QKV GEMM -> g_q/g_k/g_v (head-major).
    {
        dim3 grid(3 * Cn / 128, BTn / 128);   // (24, 32)
        gemm_cp<0><<<grid, 128, GSMEM_SZ>>>(nullptr, wt, b_attn, nullptr, BTn, 3 * Cn, Cn);
    }
    // 2) Causal flash attention -> g_y (tf32-rounded).
    {
        dim3 grid(Bn * Hn, Tn / 64);
        attn_mma<<<grid, 128>>>();
    }
    // 3) Projection GEMM: g_y @ w_proj + b_proj -> out.
    {
        dim3 grid(Cn / 128, BTn / 128);       // (8, 32)
        gemm_cp<1><<<grid, 128, GSMEM_SZ>>>(nullptr, wp, b_proj, out, BTn, Cn, Cn);
    }
}